// round 4
// baseline (speedup 1.0000x reference)
#include <cuda_runtime.h>
#include <cuda_bf16.h>

// ---------------------------------------------------------------------------
// GCN (3 layers) on GB300.
//   deg[i]    = 1 + #incoming edges          (self loops included)
//   dinv[i]   = rsqrt(deg[i])
//   layer(x,W,b): h = x@W ;  out[i] = sum_{e: dst=i} dinv[src]*dinv[i]*h[src]
//                                     + dinv[i]^2 * h[i] + b
//   relu on layers 1,2.
//
// Strategy: build dst-CSR once per call (histogram + 1-block scan + scatter),
// dense fp32 SGEMM (128x128x8 register-tiled), then per-node block reduction
// for aggregation (no float atomics; h fits in L2 so gathers are L2 hits).
// ---------------------------------------------------------------------------

#define NNODES 50000
#define NEDGES 500000
#define DIN    128
#define DHID   256

// Scratch (static device globals: allocation-free, graph-capture safe)
__device__ float g_h[(size_t)NNODES * DHID];   // GEMM output / SpMM input
__device__ float g_t[(size_t)NNODES * DHID];   // SpMM output / next GEMM input
__device__ int   g_cnt[NNODES];
__device__ float g_dinv[NNODES];
__device__ int   g_rowptr[NNODES + 1];
__device__ int   g_cursor[NNODES];
__device__ int   g_col[NEDGES];
__device__ float g_w[NEDGES];

// ------------------------------ CSR build ---------------------------------

__global__ void k_zero(int* __restrict__ cnt, int n) {
    int i = blockIdx.x * blockDim.x + threadIdx.x;
    if (i < n) cnt[i] = 0;
}

__global__ void k_hist(const int* __restrict__ dst, int e, int* __restrict__ cnt) {
    int i = blockIdx.x * blockDim.x + threadIdx.x;
    if (i < e) atomicAdd(&cnt[dst[i]], 1);
}

__global__ void k_dinv(const int* __restrict__ cnt, float* __restrict__ dinv, int n) {
    int i = blockIdx.x * blockDim.x + threadIdx.x;
    if (i < n) dinv[i] = rsqrtf((float)(cnt[i] + 1));   // +1 = self loop
}

// Exclusive scan of cnt[0..n) into rowptr[0..n], single block of 1024 threads.
__global__ __launch_bounds__(1024) void k_scan(const int* __restrict__ cnt,
                                               int* __restrict__ rowptr, int n) {
    __shared__ int sums[1024];
    int t = threadIdx.x;
    int per = (n + 1023) / 1024;
    int start = t * per;
    int end = min(start + per, n);
    int local = 0;
    for (int i = start; i < end; ++i) local += cnt[i];
    sums[t] = local;
    __syncthreads();
    // Hillis-Steele inclusive scan
    for (int off = 1; off < 1024; off <<= 1) {
        int v = (t >= off) ? sums[t - off] : 0;
        __syncthreads();
        sums[t] += v;
        __syncthreads();
    }
    int run = (t == 0) ? 0 : sums[t - 1];
    for (int i = start; i < end; ++i) { rowptr[i] = run; run += cnt[i]; }
    if (t == 1023) rowptr[n] = sums[1023];
}

__global__ void k_cursor(const int* __restrict__ rowptr, int* __restrict__ cur, int n) {
    int i = blockIdx.x * blockDim.x + threadIdx.x;
    if (i < n) cur[i] = rowptr[i];
}

__global__ void k_scatter(const int* __restrict__ src, const int* __restrict__ dst, int e,
                          int* __restrict__ cur, int* __restrict__ col,
                          float* __restrict__ w, const float* __restrict__ dinv) {
    int i = blockIdx.x * blockDim.x + threadIdx.x;
    if (i < e) {
        int d = dst[i], s = src[i];
        int pos = atomicAdd(&cur[d], 1);
        col[pos] = s;
        w[pos]   = dinv[s] * dinv[d];
    }
}

// ------------------------------ SGEMM (fp32) -------------------------------
// C[M,N] = A[M,K] @ B[K,N], row-major. BM=128, BN=128, BK=8, TM=TN=8, 256 thr.
// N is always a multiple of 128; K a multiple of 8; M guarded.

#define BM 128
#define BN 128
#define BK 8
#define TM 8
#define TN 8

__global__ __launch_bounds__(256) void k_sgemm(const float* __restrict__ A,
                                               const float* __restrict__ B,
                                               float* __restrict__ C,
                                               int M, int N, int K) {
    __shared__ float As[BK][BM];
    __shared__ float Bs[BK][BN];

    const int tid = threadIdx.x;
    const int blockRow = blockIdx.y;
    const int blockCol = blockIdx.x;

    const int innerRowA = tid >> 1;          // 0..127
    const int innerColA = (tid & 1) * 4;     // 0 or 4
    const int innerRowB = tid >> 5;          // 0..7
    const int innerColB = (tid & 31) * 4;    // 0..124
    const int threadRow = tid >> 4;          // 0..15
    const int threadCol = tid & 15;          // 0..15

    const int rowA = blockRow * BM + innerRowA;
    const float* Ab = A + (size_t)blockRow * BM * K;
    const float* Bb = B + blockCol * BN;

    float acc[TM][TN];
#pragma unroll
    for (int i = 0; i < TM; ++i)
#pragma unroll
        for (int j = 0; j < TN; ++j) acc[i][j] = 0.0f;

    for (int k0 = 0; k0 < K; k0 += BK) {
        float4 av = make_float4(0.f, 0.f, 0.f, 0.f);
        if (rowA < M)
            av = *reinterpret_cast<const float4*>(&Ab[(size_t)innerRowA * K + k0 + innerColA]);
        As[innerColA + 0][innerRowA] = av.x;
        As[innerColA + 1][innerRowA] = av.y;
        As[innerColA + 2][innerRowA] = av.z;
        As[innerColA + 3][innerRowA] = av.w;

        float4 bv = *reinterpret_cast<const float4*>(&Bb[(size_t)(k0 + innerRowB) * N + innerColB]);
        *reinterpret_cast<float4*>(&Bs[innerRowB][innerColB]) = bv;

        __syncthreads();

#pragma unroll
        for (int k = 0; k < BK; ++k) {
            float regM[TM], regN[TN];
#pragma unroll
            for (int i = 0; i < TM; ++i) regM[i] = As[k][threadRow * TM + i];
#pragma unroll
            for (int j = 0; j < TN; ++j) regN[j] = Bs[k][threadCol * TN + j];
#pragma unroll
            for (int i = 0; i < TM; ++i)
#pragma unroll
                for (int j = 0; j < TN; ++j) acc[i][j] += regM[i] * regN[j];
        }
        __syncthreads();
    }

#pragma unroll
    for (int i = 0; i < TM; ++i) {
        int row = blockRow * BM + threadRow * TM + i;
        if (row < M) {
            float* Cr = C + (size_t)row * N + blockCol * BN + threadCol * TN;
#pragma unroll
            for (int j = 0; j < TN; j += 4) {
                float4 v = make_float4(acc[i][j], acc[i][j + 1], acc[i][j + 2], acc[i][j + 3]);
                *reinterpret_cast<float4*>(&Cr[j]) = v;
            }
        }
    }
}

// --------------------------- Sparse aggregation ----------------------------
// One block (256 threads) per node; thread c owns output column c.
// out[node,c] = dinv^2*h[node,c] + sum_e w[e]*h[col[e],c] + bias[c]  (opt relu)

__global__ __launch_bounds__(256) void k_spmm(const float* __restrict__ h,
                                              const int* __restrict__ rowptr,
                                              const int* __restrict__ col,
                                              const float* __restrict__ w,
                                              const float* __restrict__ dinv,
                                              const float* __restrict__ bias,
                                              float* __restrict__ out,
                                              int do_relu) {
    const int node = blockIdx.x;
    const int c = threadIdx.x;

    const float di = dinv[node];
    float acc = di * di * __ldg(&h[(size_t)node * DHID + c]);

    const int s = rowptr[node];
    const int e = rowptr[node + 1];
    for (int j = s; j < e; ++j) {
        const int   sc = __ldg(&col[j]);
        const float ww = __ldg(&w[j]);
        acc += ww * __ldg(&h[(size_t)sc * DHID + c]);
    }
    acc += __ldg(&bias[c]);
    if (do_relu) acc = fmaxf(acc, 0.0f);
    out[(size_t)node * DHID + c] = acc;
}

// ------------------------------- launcher ----------------------------------

extern "C" void kernel_launch(void* const* d_in, const int* in_sizes, int n_in,
                              void* d_out, int out_size) {
    const float* x  = (const float*)d_in[0];
    const int*   ei = (const int*)d_in[1];
    const float* W1 = (const float*)d_in[2];
    const float* b1 = (const float*)d_in[3];
    const float* W2 = (const float*)d_in[4];
    const float* b2 = (const float*)d_in[5];
    const float* W3 = (const float*)d_in[6];
    const float* b3 = (const float*)d_in[7];
    float* out = (float*)d_out;

    const int n = NNODES;
    const int e = NEDGES;
    const int* srcp = ei;        // edge_index[0]
    const int* dstp = ei + e;    // edge_index[1]

    void *p_h, *p_t, *p_cnt, *p_dinv, *p_rowptr, *p_cursor, *p_col, *p_w;
    cudaGetSymbolAddress(&p_h, g_h);
    cudaGetSymbolAddress(&p_t, g_t);
    cudaGetSymbolAddress(&p_cnt, g_cnt);
    cudaGetSymbolAddress(&p_dinv, g_dinv);
    cudaGetSymbolAddress(&p_rowptr, g_rowptr);
    cudaGetSymbolAddress(&p_cursor, g_cursor);
    cudaGetSymbolAddress(&p_col, g_col);
    cudaGetSymbolAddress(&p_w, g_w);

    float* hbuf = (float*)p_h;
    float* tbuf = (float*)p_t;
    int*   cnt  = (int*)p_cnt;
    float* dinv = (float*)p_dinv;
    int*   rowp = (int*)p_rowptr;
    int*   curs = (int*)p_cursor;
    int*   col  = (int*)p_col;
    float* w    = (float*)p_w;

    const int TB = 256;
    // ---- CSR build (per call; cheap) ----
    k_zero   <<<(n + TB - 1) / TB, TB>>>(cnt, n);
    k_hist   <<<(e + TB - 1) / TB, TB>>>(dstp, e, cnt);
    k_dinv   <<<(n + TB - 1) / TB, TB>>>(cnt, dinv, n);
    k_scan   <<<1, 1024>>>(cnt, rowp, n);
    k_cursor <<<(n + TB - 1) / TB, TB>>>(rowp, curs, n);
    k_scatter<<<(e + TB - 1) / TB, TB>>>(srcp, dstp, e, curs, col, w, dinv);

    dim3 gblk(256);
    dim3 ggrid(DHID / BN, (n + BM - 1) / BM);

    // ---- Layer 1 ----
    k_sgemm<<<ggrid, gblk>>>(x, W1, hbuf, n, DHID, DIN);
    k_spmm <<<n, DHID>>>(hbuf, rowp, col, w, dinv, b1, tbuf, 1);
    // ---- Layer 2 ----
    k_sgemm<<<ggrid, gblk>>>(tbuf, W2, hbuf, n, DHID, DHID);
    k_spmm <<<n, DHID>>>(hbuf, rowp, col, w, dinv, b2, tbuf, 1);
    // ---- Layer 3 ----
    k_sgemm<<<ggrid, gblk>>>(tbuf, W3, hbuf, n, DHID, DHID);
    k_spmm <<<n, DHID>>>(hbuf, rowp, col, w, dinv, b3, out, 0);
}

// round 5
// speedup vs baseline: 1.0025x; 1.0025x over previous
#include <cuda_runtime.h>
#include <cuda_bf16.h>

// ---------------------------------------------------------------------------
// GCN (3 layers) on GB300.
//   deg[i]    = 1 + #incoming edges          (self loops included)
//   dinv[i]   = rsqrt(deg[i])
//   layer(x,W,b): h = x@W ;  out[i] = sum_{e: dst=i} dinv[src]*dinv[i]*h[src]
//                                     + dinv[i]^2 * h[i] + b
//   relu on layers 1,2.
//
// Strategy: build dst-CSR once per call (histogram + 1-block scan + scatter),
// dense fp32 SGEMM (128x128x8 register-tiled), then per-node block reduction
// for aggregation (no float atomics; h fits in L2 so gathers are L2 hits).
// ---------------------------------------------------------------------------

#define NNODES 50000
#define NEDGES 500000
#define DIN    128
#define DHID   256

// Scratch (static device globals: allocation-free, graph-capture safe)
__device__ float g_h[(size_t)NNODES * DHID];   // GEMM output / SpMM input
__device__ float g_t[(size_t)NNODES * DHID];   // SpMM output / next GEMM input
__device__ int   g_cnt[NNODES];
__device__ float g_dinv[NNODES];
__device__ int   g_rowptr[NNODES + 1];
__device__ int   g_cursor[NNODES];
__device__ int   g_col[NEDGES];
__device__ float g_w[NEDGES];

// ------------------------------ CSR build ---------------------------------

__global__ void k_zero(int* __restrict__ cnt, int n) {
    int i = blockIdx.x * blockDim.x + threadIdx.x;
    if (i < n) cnt[i] = 0;
}

__global__ void k_hist(const int* __restrict__ dst, int e, int* __restrict__ cnt) {
    int i = blockIdx.x * blockDim.x + threadIdx.x;
    if (i < e) atomicAdd(&cnt[dst[i]], 1);
}

__global__ void k_dinv(const int* __restrict__ cnt, float* __restrict__ dinv, int n) {
    int i = blockIdx.x * blockDim.x + threadIdx.x;
    if (i < n) dinv[i] = rsqrtf((float)(cnt[i] + 1));   // +1 = self loop
}

// Exclusive scan of cnt[0..n) into rowptr[0..n], single block of 1024 threads.
__global__ __launch_bounds__(1024) void k_scan(const int* __restrict__ cnt,
                                               int* __restrict__ rowptr, int n) {
    __shared__ int sums[1024];
    int t = threadIdx.x;
    int per = (n + 1023) / 1024;
    int start = t * per;
    int end = min(start + per, n);
    int local = 0;
    for (int i = start; i < end; ++i) local += cnt[i];
    sums[t] = local;
    __syncthreads();
    // Hillis-Steele inclusive scan
    for (int off = 1; off < 1024; off <<= 1) {
        int v = (t >= off) ? sums[t - off] : 0;
        __syncthreads();
        sums[t] += v;
        __syncthreads();
    }
    int run = (t == 0) ? 0 : sums[t - 1];
    for (int i = start; i < end; ++i) { rowptr[i] = run; run += cnt[i]; }
    if (t == 1023) rowptr[n] = sums[1023];
}

__global__ void k_cursor(const int* __restrict__ rowptr, int* __restrict__ cur, int n) {
    int i = blockIdx.x * blockDim.x + threadIdx.x;
    if (i < n) cur[i] = rowptr[i];
}

__global__ void k_scatter(const int* __restrict__ src, const int* __restrict__ dst, int e,
                          int* __restrict__ cur, int* __restrict__ col,
                          float* __restrict__ w, const float* __restrict__ dinv) {
    int i = blockIdx.x * blockDim.x + threadIdx.x;
    if (i < e) {
        int d = dst[i], s = src[i];
        int pos = atomicAdd(&cur[d], 1);
        col[pos] = s;
        w[pos]   = dinv[s] * dinv[d];
    }
}

// ------------------------------ SGEMM (fp32) -------------------------------
// C[M,N] = A[M,K] @ B[K,N], row-major. BM=128, BN=128, BK=8, TM=TN=8, 256 thr.
// N is always a multiple of 128; K a multiple of 8; M guarded.

#define BM 128
#define BN 128
#define BK 8
#define TM 8
#define TN 8

__global__ __launch_bounds__(256) void k_sgemm(const float* __restrict__ A,
                                               const float* __restrict__ B,
                                               float* __restrict__ C,
                                               int M, int N, int K) {
    __shared__ float As[BK][BM];
    __shared__ float Bs[BK][BN];

    const int tid = threadIdx.x;
    const int blockRow = blockIdx.y;
    const int blockCol = blockIdx.x;

    const int innerRowA = tid >> 1;          // 0..127
    const int innerColA = (tid & 1) * 4;     // 0 or 4
    const int innerRowB = tid >> 5;          // 0..7
    const int innerColB = (tid & 31) * 4;    // 0..124
    const int threadRow = tid >> 4;          // 0..15
    const int threadCol = tid & 15;          // 0..15

    const int rowA = blockRow * BM + innerRowA;
    const float* Ab = A + (size_t)blockRow * BM * K;
    const float* Bb = B + blockCol * BN;

    float acc[TM][TN];
#pragma unroll
    for (int i = 0; i < TM; ++i)
#pragma unroll
        for (int j = 0; j < TN; ++j) acc[i][j] = 0.0f;

    for (int k0 = 0; k0 < K; k0 += BK) {
        float4 av = make_float4(0.f, 0.f, 0.f, 0.f);
        if (rowA < M)
            av = *reinterpret_cast<const float4*>(&Ab[(size_t)innerRowA * K + k0 + innerColA]);
        As[innerColA + 0][innerRowA] = av.x;
        As[innerColA + 1][innerRowA] = av.y;
        As[innerColA + 2][innerRowA] = av.z;
        As[innerColA + 3][innerRowA] = av.w;

        float4 bv = *reinterpret_cast<const float4*>(&Bb[(size_t)(k0 + innerRowB) * N + innerColB]);
        *reinterpret_cast<float4*>(&Bs[innerRowB][innerColB]) = bv;

        __syncthreads();

#pragma unroll
        for (int k = 0; k < BK; ++k) {
            float regM[TM], regN[TN];
#pragma unroll
            for (int i = 0; i < TM; ++i) regM[i] = As[k][threadRow * TM + i];
#pragma unroll
            for (int j = 0; j < TN; ++j) regN[j] = Bs[k][threadCol * TN + j];
#pragma unroll
            for (int i = 0; i < TM; ++i)
#pragma unroll
                for (int j = 0; j < TN; ++j) acc[i][j] += regM[i] * regN[j];
        }
        __syncthreads();
    }

#pragma unroll
    for (int i = 0; i < TM; ++i) {
        int row = blockRow * BM + threadRow * TM + i;
        if (row < M) {
            float* Cr = C + (size_t)row * N + blockCol * BN + threadCol * TN;
#pragma unroll
            for (int j = 0; j < TN; j += 4) {
                float4 v = make_float4(acc[i][j], acc[i][j + 1], acc[i][j + 2], acc[i][j + 3]);
                *reinterpret_cast<float4*>(&Cr[j]) = v;
            }
        }
    }
}

// --------------------------- Sparse aggregation ----------------------------
// One block (256 threads) per node; thread c owns output column c.
// out[node,c] = dinv^2*h[node,c] + sum_e w[e]*h[col[e],c] + bias[c]  (opt relu)

__global__ __launch_bounds__(256) void k_spmm(const float* __restrict__ h,
                                              const int* __restrict__ rowptr,
                                              const int* __restrict__ col,
                                              const float* __restrict__ w,
                                              const float* __restrict__ dinv,
                                              const float* __restrict__ bias,
                                              float* __restrict__ out,
                                              int do_relu) {
    const int node = blockIdx.x;
    const int c = threadIdx.x;

    const float di = dinv[node];
    float acc = di * di * __ldg(&h[(size_t)node * DHID + c]);

    const int s = rowptr[node];
    const int e = rowptr[node + 1];
    for (int j = s; j < e; ++j) {
        const int   sc = __ldg(&col[j]);
        const float ww = __ldg(&w[j]);
        acc += ww * __ldg(&h[(size_t)sc * DHID + c]);
    }
    acc += __ldg(&bias[c]);
    if (do_relu) acc = fmaxf(acc, 0.0f);
    out[(size_t)node * DHID + c] = acc;
}

// ------------------------------- launcher ----------------------------------

extern "C" void kernel_launch(void* const* d_in, const int* in_sizes, int n_in,
                              void* d_out, int out_size) {
    const float* x  = (const float*)d_in[0];
    const int*   ei = (const int*)d_in[1];
    const float* W1 = (const float*)d_in[2];
    const float* b1 = (const float*)d_in[3];
    const float* W2 = (const float*)d_in[4];
    const float* b2 = (const float*)d_in[5];
    const float* W3 = (const float*)d_in[6];
    const float* b3 = (const float*)d_in[7];
    float* out = (float*)d_out;

    const int n = NNODES;
    const int e = NEDGES;
    const int* srcp = ei;        // edge_index[0]
    const int* dstp = ei + e;    // edge_index[1]

    void *p_h, *p_t, *p_cnt, *p_dinv, *p_rowptr, *p_cursor, *p_col, *p_w;
    cudaGetSymbolAddress(&p_h, g_h);
    cudaGetSymbolAddress(&p_t, g_t);
    cudaGetSymbolAddress(&p_cnt, g_cnt);
    cudaGetSymbolAddress(&p_dinv, g_dinv);
    cudaGetSymbolAddress(&p_rowptr, g_rowptr);
    cudaGetSymbolAddress(&p_cursor, g_cursor);
    cudaGetSymbolAddress(&p_col, g_col);
    cudaGetSymbolAddress(&p_w, g_w);

    float* hbuf = (float*)p_h;
    float* tbuf = (float*)p_t;
    int*   cnt  = (int*)p_cnt;
    float* dinv = (float*)p_dinv;
    int*   rowp = (int*)p_rowptr;
    int*   curs = (int*)p_cursor;
    int*   col  = (int*)p_col;
    float* w    = (float*)p_w;

    const int TB = 256;
    // ---- CSR build (per call; cheap) ----
    k_zero   <<<(n + TB - 1) / TB, TB>>>(cnt, n);
    k_hist   <<<(e + TB - 1) / TB, TB>>>(dstp, e, cnt);
    k_dinv   <<<(n + TB - 1) / TB, TB>>>(cnt, dinv, n);
    k_scan   <<<1, 1024>>>(cnt, rowp, n);
    k_cursor <<<(n + TB - 1) / TB, TB>>>(rowp, curs, n);
    k_scatter<<<(e + TB - 1) / TB, TB>>>(srcp, dstp, e, curs, col, w, dinv);

    dim3 gblk(256);
    dim3 ggrid(DHID / BN, (n + BM - 1) / BM);

    // ---- Layer 1 ----
    k_sgemm<<<ggrid, gblk>>>(x, W1, hbuf, n, DHID, DIN);
    k_spmm <<<n, DHID>>>(hbuf, rowp, col, w, dinv, b1, tbuf, 1);
    // ---- Layer 2 ----
    k_sgemm<<<ggrid, gblk>>>(tbuf, W2, hbuf, n, DHID, DHID);
    k_spmm <<<n, DHID>>>(hbuf, rowp, col, w, dinv, b2, tbuf, 1);
    // ---- Layer 3 ----
    k_sgemm<<<ggrid, gblk>>>(tbuf, W3, hbuf, n, DHID, DHID);
    k_spmm <<<n, DHID>>>(hbuf, rowp, col, w, dinv, b3, out, 0);
}